// round 13
// baseline (speedup 1.0000x reference)
#include <cuda_runtime.h>
#include <cuda_bf16.h>

// Problem constants:
//   B = 128 rows, L = 262144 input cols
//   CROP_NUM = 26214, OUT_LEN = 235930
//   out[i, j] = audio[i, j]             for j <  starts[i]
//   out[i, j] = audio[i, j + CROP_NUM]  for j >= starts[i]
//
// Persistent grid-stride formulation: 1184 CTAs (148 SMs x 8) loop over the
// 58 x 128 = 7424 tiles instead of launching one CTA per tile. Each tile is
// 1024 float4 vectors of one row. `start` is tile-uniform. OUT_LEN % 4 == 2,
// so odd rows get a 2-element alignment prefix; 58982 aligned float4 vectors
// per row + 2 scalar leftovers handled by tile 0 of each row.
//
// Measured policy matrix (kernel us): default 35.1-36.4 | __stcs 36.1 |
// evict_last 36.0 | __stwt 35.5 -> all within noise; __stwt kept.

#define L_IN     262144u
#define CROP_NUM 26214u
#define OUT_LEN  235930u
#define ROW_VECS 58982u          // full aligned float4 vectors per row
#define BLK_VECS 1024u           // 256 threads * ILP 4
#define TILES_X  58u             // ceil(58982 / 1024)
#define N_TILES  (TILES_X * 128u)  // 7424
#define GRID_SZ  1184u           // 148 SMs * 8 resident CTAs

__global__ __launch_bounds__(256)
void Crop_21345987461560_kernel(const float* __restrict__ audio,
                                const int*   __restrict__ starts,
                                float*       __restrict__ out)
{
    for (unsigned int tile = blockIdx.x; tile < N_TILES; tile += GRID_SZ) {
        const unsigned int row = tile / TILES_X;          // const-div
        const unsigned int tx  = tile - row * TILES_X;
        const unsigned int pre = (row & 1u) << 1;         // 0 or 2
        const unsigned int start = (unsigned int)__ldg(&starts[row]);
        const float* __restrict__ rowp = audio + (size_t)row * L_IN;

        // row*OUT_LEN + pre is a multiple of 4 -> aligned float4 view.
        float4* __restrict__ out4 =
            reinterpret_cast<float4*>(out + (size_t)row * OUT_LEN + pre);

        const unsigned int v0 = tx * BLK_VECS + threadIdx.x;

        #pragma unroll
        for (unsigned int k = 0; k < 4u; ++k) {
            unsigned int v = v0 + k * 256u;
            if (v < ROW_VECS) {
                unsigned int j0 = pre + v * 4u;           // even
                float4 r;
                if (j0 >= start) {
                    // Fully post-crop: contiguous shifted -> 2x LDG.64
                    const float2* p = reinterpret_cast<const float2*>(rowp + j0 + CROP_NUM);
                    float2 a = __ldg(p);
                    float2 b = __ldg(p + 1);
                    r = make_float4(a.x, a.y, b.x, b.y);
                } else if (j0 + 3u < start) {
                    // Fully pre-crop: contiguous -> 2x LDG.64
                    const float2* p = reinterpret_cast<const float2*>(rowp + j0);
                    float2 a = __ldg(p);
                    float2 b = __ldg(p + 1);
                    r = make_float4(a.x, a.y, b.x, b.y);
                } else {
                    // Straddles the crop boundary (one vector per row)
                    unsigned int j;
                    j = j0;      r.x = __ldg(&rowp[j + (j >= start ? CROP_NUM : 0u)]);
                    j = j0 + 1u; r.y = __ldg(&rowp[j + (j >= start ? CROP_NUM : 0u)]);
                    j = j0 + 2u; r.z = __ldg(&rowp[j + (j >= start ? CROP_NUM : 0u)]);
                    j = j0 + 3u; r.w = __ldg(&rowp[j + (j >= start ? CROP_NUM : 0u)]);
                }
                __stwt(out4 + v, r);
            }
        }

        // 2 leftover scalar elements per row: prefix (j=0,1) on odd rows,
        // suffix (j=OUT_LEN-2, OUT_LEN-1) on even rows. Done by tile tx==0.
        if (tx == 0 && threadIdx.x < 2u) {
            unsigned int j = (row & 1u) ? threadIdx.x
                                        : (OUT_LEN - 2u + threadIdx.x);
            float val = __ldg(&rowp[j + (j >= start ? CROP_NUM : 0u)]);
            __stwt(out + (size_t)row * OUT_LEN + j, val);
        }
    }
}

extern "C" void kernel_launch(void* const* d_in, const int* in_sizes, int n_in,
                              void* d_out, int out_size)
{
    const float* audio  = (const float*)d_in[0];   // [128, 262144] float32
    const int*   starts = (const int*)d_in[1];     // [128] int32
    float*       out    = (float*)d_out;           // [128, 235930] float32

    Crop_21345987461560_kernel<<<GRID_SZ, 256>>>(audio, starts, out);
}